// round 4
// baseline (speedup 1.0000x reference)
#include <cuda_runtime.h>

// RoPE_90847148245015 — block-sparse RoPE rotation, pure streaming kernel.
// feats: [B=16, C=256, H=128, W=128] fp32   (d_in[0])
// R:     [H=128, C=256, C=256] fp32          (d_in[1])
// out:   [B=16, C=256, H=128, W=128] fp32
//
// out[b,2k,  h,w] = R[h,2k,2k]    *f[b,2k,h,w] + R[h,2k,2k+1]*f[b,2k+1,h,w]
// out[b,2k+1,h,w] = R[h,2k+1,2k+1]*f[b,2k+1,h,w] + R[h,2k+1,2k]*f[b,2k,h,w]
//
// R4: R2's memory shape (x2 batch unroll = 4 independent LDG.128, occ ~81%,
// established optimal across R1/R2/R3) + persistent grid-stride launch:
// 1216 CTAs (152 SMs x 8 resident) in ONE wave, each looping ~13.5 tiles.
// Removes ~14 CTA-wave launch/drain transitions; load stream never restarts.

__global__ __launch_bounds__(256) void rope_rot_kernel(
    const float* __restrict__ feats,
    const float* __restrict__ R,
    float* __restrict__ out)
{
    const int TOTAL  = 8 * 128 * 128 * 32;      // (B/2)*K*H*(W/4) = 4,194,304
    const int STRIDE = 1216 * 256;              // one full resident wave

    const float4* __restrict__ f4 = reinterpret_cast<const float4*>(feats);
    float4* __restrict__ o4 = reinterpret_cast<float4*>(out);

    for (int idx = blockIdx.x * 256 + threadIdx.x; idx < TOTAL; idx += STRIDE) {
        // idx layout: [b3:3][k:7][h:7][w4:5]  (b in {b3, b3+8})
        const int w4 = idx & 31;
        const int h  = (idx >> 5) & 127;
        const int k  = (idx >> 12) & 127;
        const int b3 = idx >> 19;               // 0..7

        // R[h, 2k, 2k] ; element stride: h*65536 + row*256 + col
        const int rbase = (h << 16) + (k << 9) + (k << 1);
        const float ce = __ldg(R + rbase);        // cos  (even row)
        const float se = __ldg(R + rbase + 1);    // -sin
        const float so = __ldg(R + rbase + 256);  // +sin
        const float co = __ldg(R + rbase + 257);  // cos  (odd row)

        // float4 indexing: plane stride 4096, row stride 32
        const int base0 = (((b3 << 8) + (k << 1)) << 12) + (h << 5) + w4;
        const int base1 = base0 + (8 << 20);      // b3+8

        const float4 fe0 = __ldcs(f4 + base0);
        const float4 fo0 = __ldcs(f4 + base0 + 4096);
        const float4 fe1 = __ldcs(f4 + base1);
        const float4 fo1 = __ldcs(f4 + base1 + 4096);

        float4 oe0, oo0, oe1, oo1;
        oe0.x = fmaf(ce, fe0.x, se * fo0.x);
        oe0.y = fmaf(ce, fe0.y, se * fo0.y);
        oe0.z = fmaf(ce, fe0.z, se * fo0.z);
        oe0.w = fmaf(ce, fe0.w, se * fo0.w);
        oo0.x = fmaf(co, fo0.x, so * fe0.x);
        oo0.y = fmaf(co, fo0.y, so * fe0.y);
        oo0.z = fmaf(co, fo0.z, so * fe0.z);
        oo0.w = fmaf(co, fo0.w, so * fe0.w);

        oe1.x = fmaf(ce, fe1.x, se * fo1.x);
        oe1.y = fmaf(ce, fe1.y, se * fo1.y);
        oe1.z = fmaf(ce, fe1.z, se * fo1.z);
        oe1.w = fmaf(ce, fe1.w, se * fo1.w);
        oo1.x = fmaf(co, fo1.x, so * fe1.x);
        oo1.y = fmaf(co, fo1.y, so * fe1.y);
        oo1.z = fmaf(co, fo1.z, so * fe1.z);
        oo1.w = fmaf(co, fo1.w, so * fe1.w);

        __stcs(o4 + base0,        oe0);
        __stcs(o4 + base0 + 4096, oo0);
        __stcs(o4 + base1,        oe1);
        __stcs(o4 + base1 + 4096, oo1);
    }
}

extern "C" void kernel_launch(void* const* d_in, const int* in_sizes, int n_in,
                              void* d_out, int out_size) {
    const float* feats = (const float*)d_in[0];
    const float* R     = (const float*)d_in[1];
    float* out         = (float*)d_out;

    rope_rot_kernel<<<1216, 256>>>(feats, R, out);
}

// round 5
// speedup vs baseline: 1.0599x; 1.0599x over previous
#include <cuda_runtime.h>

// RoPE_90847148245015 — block-sparse RoPE rotation, pure streaming kernel.
// feats: [B=16, C=256, H=128, W=128] fp32   (d_in[0])
// R:     [H=128, C=256, C=256] fp32          (d_in[1])
// out:   [B=16, C=256, H=128, W=128] fp32
//
// out[b,2k,  h,w] = R[h,2k,2k]    *f[b,2k,h,w] + R[h,2k,2k+1]*f[b,2k+1,h,w]
// out[b,2k+1,h,w] = R[h,2k+1,2k+1]*f[b,2k+1,h,w] + R[h,2k+1,2k]*f[b,2k,h,w]
//
// R5: exact R2 shape (best: x2 batch unroll, 4 independent LDG.128, occ 81%)
// with ONE delta: __stcs -> __stwt (write-through). Stores are full coalesced
// 512B/warp sectors; write-through skips L2 write-allocate entirely, freeing
// L2 for the read stream and removing dirty-writeback scheduling.

__global__ __launch_bounds__(256) void rope_rot_kernel(
    const float* __restrict__ feats,
    const float* __restrict__ R,
    float* __restrict__ out)
{
    const int idx = blockIdx.x * 256 + threadIdx.x;
    // idx layout: [b3:3][k:7][h:7][w4:5]  (b in {b3, b3+8})
    const int w4 = idx & 31;
    const int h  = (idx >> 5) & 127;
    const int k  = (idx >> 12) & 127;
    const int b3 = idx >> 19;          // 0..7

    // R[h, 2k, 2k] ; element stride: h*65536 + row*256 + col
    const int rbase = (h << 16) + (k << 9) + (k << 1);
    const float ce = __ldg(R + rbase);        // cos  (even row)
    const float se = __ldg(R + rbase + 1);    // -sin
    const float so = __ldg(R + rbase + 256);  // +sin
    const float co = __ldg(R + rbase + 257);  // cos  (odd row)

    // float4 indexing: plane stride 4096, row stride 32, batch stride 256*4096
    const int base0 = (((b3 << 8) + (k << 1)) << 12) + (h << 5) + w4;
    const int base1 = base0 + (8 << 20);      // b3+8

    const float4* __restrict__ f4 = reinterpret_cast<const float4*>(feats);
    float4* __restrict__ o4 = reinterpret_cast<float4*>(out);

    // 4 independent streaming loads, front-batched for MLP
    const float4 fe0 = __ldcs(f4 + base0);
    const float4 fo0 = __ldcs(f4 + base0 + 4096);
    const float4 fe1 = __ldcs(f4 + base1);
    const float4 fo1 = __ldcs(f4 + base1 + 4096);

    float4 oe0, oo0, oe1, oo1;
    oe0.x = fmaf(ce, fe0.x, se * fo0.x);
    oe0.y = fmaf(ce, fe0.y, se * fo0.y);
    oe0.z = fmaf(ce, fe0.z, se * fo0.z);
    oe0.w = fmaf(ce, fe0.w, se * fo0.w);
    oo0.x = fmaf(co, fo0.x, so * fe0.x);
    oo0.y = fmaf(co, fo0.y, so * fe0.y);
    oo0.z = fmaf(co, fo0.z, so * fe0.z);
    oo0.w = fmaf(co, fo0.w, so * fe0.w);

    oe1.x = fmaf(ce, fe1.x, se * fo1.x);
    oe1.y = fmaf(ce, fe1.y, se * fo1.y);
    oe1.z = fmaf(ce, fe1.z, se * fo1.z);
    oe1.w = fmaf(ce, fe1.w, se * fo1.w);
    oo1.x = fmaf(co, fo1.x, so * fe1.x);
    oo1.y = fmaf(co, fo1.y, so * fe1.y);
    oo1.z = fmaf(co, fo1.z, so * fe1.z);
    oo1.w = fmaf(co, fo1.w, so * fe1.w);

    __stwt(o4 + base0,        oe0);
    __stwt(o4 + base0 + 4096, oo0);
    __stwt(o4 + base1,        oe1);
    __stwt(o4 + base1 + 4096, oo1);
}

extern "C" void kernel_launch(void* const* d_in, const int* in_sizes, int n_in,
                              void* d_out, int out_size) {
    const float* feats = (const float*)d_in[0];
    const float* R     = (const float*)d_in[1];
    float* out         = (float*)d_out;

    // threads: (B/2)*K*H*(W/4) = 8*128*128*32 = 4,194,304
    const int total = 8 * 128 * 128 * 32;
    rope_rot_kernel<<<total / 256, 256>>>(feats, R, out);
}

// round 6
// speedup vs baseline: 1.0835x; 1.0222x over previous
#include <cuda_runtime.h>

// RoPE_90847148245015 — block-sparse RoPE rotation, pure streaming kernel.
// feats: [B=16, C=256, H=128, W=128] fp32   (d_in[0])
// R:     [H=128, C=256, C=256] fp32          (d_in[1])
// out:   [B=16, C=256, H=128, W=128] fp32
//
// out[b,2k,  h,w] = R[h,2k,2k]    *f[b,2k,h,w] + R[h,2k,2k+1]*f[b,2k+1,h,w]
// out[b,2k+1,h,w] = R[h,2k+1,2k+1]*f[b,2k+1,h,w] + R[h,2k+1,2k]*f[b,2k,h,w]
//
// Final form (R6): R2's memory shape — empirical optimum across 5 rounds
// (x2 batch unroll = 4 independent LDG.128, __ldcs/__stcs, occ ~80%,
// DRAM ~82% = sm_103a mixed read/write HBM ceiling) — plus vectorized
// float2 loads of the R coefficient pairs (2x LDG.64 instead of 4x LDG.32).

__global__ __launch_bounds__(256) void rope_rot_kernel(
    const float* __restrict__ feats,
    const float* __restrict__ R,
    float* __restrict__ out)
{
    const int idx = blockIdx.x * 256 + threadIdx.x;
    // idx layout: [b3:3][k:7][h:7][w4:5]  (b in {b3, b3+8})
    const int w4 = idx & 31;
    const int h  = (idx >> 5) & 127;
    const int k  = (idx >> 12) & 127;
    const int b3 = idx >> 19;          // 0..7

    // R[h, 2k, 2k]; element index rbase = h*65536 + 2k*256 + 2k (always even
    // -> 8B aligned). (ce,se) adjacent at rbase; (so,co) adjacent at rbase+256.
    const int rbase = (h << 16) + (k << 9) + (k << 1);
    const float2 r0 = __ldg(reinterpret_cast<const float2*>(R + rbase));        // {cos, -sin}
    const float2 r1 = __ldg(reinterpret_cast<const float2*>(R + rbase + 256));  // {+sin, cos}
    const float ce = r0.x, se = r0.y, so = r1.x, co = r1.y;

    // float4 indexing: plane stride 4096, row stride 32, batch stride 256*4096
    const int base0 = (((b3 << 8) + (k << 1)) << 12) + (h << 5) + w4;
    const int base1 = base0 + (8 << 20);      // b3+8

    const float4* __restrict__ f4 = reinterpret_cast<const float4*>(feats);
    float4* __restrict__ o4 = reinterpret_cast<float4*>(out);

    // 4 independent streaming loads, front-batched for MLP
    const float4 fe0 = __ldcs(f4 + base0);
    const float4 fo0 = __ldcs(f4 + base0 + 4096);
    const float4 fe1 = __ldcs(f4 + base1);
    const float4 fo1 = __ldcs(f4 + base1 + 4096);

    float4 oe0, oo0, oe1, oo1;
    oe0.x = fmaf(ce, fe0.x, se * fo0.x);
    oe0.y = fmaf(ce, fe0.y, se * fo0.y);
    oe0.z = fmaf(ce, fe0.z, se * fo0.z);
    oe0.w = fmaf(ce, fe0.w, se * fo0.w);
    oo0.x = fmaf(co, fo0.x, so * fe0.x);
    oo0.y = fmaf(co, fo0.y, so * fe0.y);
    oo0.z = fmaf(co, fo0.z, so * fe0.z);
    oo0.w = fmaf(co, fo0.w, so * fe0.w);

    oe1.x = fmaf(ce, fe1.x, se * fo1.x);
    oe1.y = fmaf(ce, fe1.y, se * fo1.y);
    oe1.z = fmaf(ce, fe1.z, se * fo1.z);
    oe1.w = fmaf(ce, fe1.w, se * fo1.w);
    oo1.x = fmaf(co, fo1.x, so * fe1.x);
    oo1.y = fmaf(co, fo1.y, so * fe1.y);
    oo1.z = fmaf(co, fo1.z, so * fe1.z);
    oo1.w = fmaf(co, fo1.w, so * fe1.w);

    __stcs(o4 + base0,        oe0);
    __stcs(o4 + base0 + 4096, oo0);
    __stcs(o4 + base1,        oe1);
    __stcs(o4 + base1 + 4096, oo1);
}

extern "C" void kernel_launch(void* const* d_in, const int* in_sizes, int n_in,
                              void* d_out, int out_size) {
    const float* feats = (const float*)d_in[0];
    const float* R     = (const float*)d_in[1];
    float* out         = (float*)d_out;

    // threads: (B/2)*K*H*(W/4) = 8*128*128*32 = 4,194,304
    const int total = 8 * 128 * 128 * 32;
    rope_rot_kernel<<<total / 256, 256>>>(feats, R, out);
}